// round 10
// baseline (speedup 1.0000x reference)
#include <cuda_runtime.h>
#include <cuda_fp16.h>
#include <cstdint>

#define D_DIM    256
#define K_DIM    512
#define TILE_M   64
#define NTILES   1024
#define NTHREADS 256
#define T_CHEAP  0.10f

// ---------------- device globals (no runtime allocs) ------------------------
__device__ __align__(16) unsigned short g_cbF[K_DIM * D_DIM];  // fp16 codebook
__device__ float g_esq[K_DIM];
__device__ float g_partials[NTILES];
__device__ unsigned int g_ticket;
__device__ int   g_mask_kind;   // 0=int32, 1=uint8, 2=float32

// ---------------- smem layout ------------------------------------------------
// persistent region
#define OFF_A     0          // z fp16: 64 rows x 512B (swizzled) = 32KB
#define OFF_B     32768      // 2 bufs x 8KB = 16KB (aliased after mainloop)
#define OFF_ESQ   49152      // 512 f
#define OFF_V1    51200      // 128 f
#define OFF_V2    51712
#define OFF_V3    52224
#define OFF_I1    52736
#define OFF_I2    53248
#define OFF_ZSQ   53760      // 64 f
#define OFF_MV    54016      // 64 f
#define SMEM_TOTAL 54272
// aliases into the (dead after mainloop) B region:
#define OFF_ZROW  (OFF_B + 0)      // 256 f
#define OFF_RV    (OFF_B + 1024)   // 256 f
#define OFF_RI    (OFF_B + 2048)   // 256 i
#define OFF_FLIST (OFF_B + 3072)   // 64 i
#define OFF_FLE   (OFF_B + 3328)   // 64 i
#define OFF_NFL   (OFF_B + 3584)   // 2 i
#define OFF_LAST  (OFF_B + 3600)   // 1 i

// ---------------- helpers ---------------------------------------------------
static __device__ __forceinline__ uint32_t smem_u32(const void* p) {
    uint32_t a;
    asm("{ .reg .u64 t; cvta.to.shared.u64 t, %1; cvt.u32.u64 %0, t; }" : "=r"(a) : "l"(p));
    return a;
}
#define LDSM_X4(r0,r1,r2,r3,addr) \
    asm volatile("ldmatrix.sync.aligned.m8n8.x4.shared.b16 {%0,%1,%2,%3}, [%4];" \
        : "=r"(r0),"=r"(r1),"=r"(r2),"=r"(r3) : "r"(addr))
#define MMA_F16(dd, a0,a1,a2,a3, b0,b1) \
    asm volatile("mma.sync.aligned.m16n8k16.row.col.f32.f16.f16.f32 " \
        "{%0,%1,%2,%3}, {%4,%5,%6,%7}, {%8,%9}, {%0,%1,%2,%3};" \
        : "+f"((dd)[0]),"+f"((dd)[1]),"+f"((dd)[2]),"+f"((dd)[3]) \
        : "r"(a0),"r"(a1),"r"(a2),"r"(a3),"r"(b0),"r"(b1))
#define CP_ASYNC16(dst, src) \
    asm volatile("cp.async.cg.shared.global [%0], [%1], 16;" :: "r"(dst), "l"(src) : "memory")
#define CP_COMMIT() asm volatile("cp.async.commit_group;" ::: "memory")
#define CP_WAIT1()  asm volatile("cp.async.wait_group 1;" ::: "memory")
#define CP_WAIT0()  asm volatile("cp.async.wait_group 0;" ::: "memory")

// ---------------- prep: codebook fp16 + ||e||^2 + mask dtype ----------------
__global__ void prep_kernel(const float* __restrict__ cb,
                            const void* __restrict__ mask, int mask_words) {
    int warp = blockIdx.x * 16 + (threadIdx.x >> 5);
    int lane = threadIdx.x & 31;
    const float4* row = (const float4*)(cb + (size_t)warp * D_DIM);
    float4 v0 = row[lane * 2], v1 = row[lane * 2 + 1];
    float vs[8] = { v0.x, v0.y, v0.z, v0.w, v1.x, v1.y, v1.z, v1.w };
    unsigned short hs[8];
    float zs = 0.f;
    #pragma unroll
    for (int e = 0; e < 8; e++) {
        __half h = __float2half_rn(vs[e]);
        hs[e] = *reinterpret_cast<unsigned short*>(&h);
        zs += vs[e] * vs[e];
    }
    uint4 P;
    P.x = (uint32_t)hs[0] | ((uint32_t)hs[1] << 16);
    P.y = (uint32_t)hs[2] | ((uint32_t)hs[3] << 16);
    P.z = (uint32_t)hs[4] | ((uint32_t)hs[5] << 16);
    P.w = (uint32_t)hs[6] | ((uint32_t)hs[7] << 16);
    *(uint4*)(g_cbF + (size_t)warp * D_DIM + lane * 8) = P;
    #pragma unroll
    for (int m = 16; m >= 1; m >>= 1) zs += __shfl_xor_sync(0xFFFFFFFFu, zs, m);
    if (lane == 0) g_esq[warp] = zs;

    if (blockIdx.x == 0) {
        __shared__ int s_int_ok, s_float_ok;
        if (threadIdx.x == 0) { s_int_ok = 1; s_float_ok = 1; }
        __syncthreads();
        if (threadIdx.x < 256) {
            const unsigned int* mw = (const unsigned int*)mask;
            int iok = 1, fok = 1;
            for (int j = 0; j < 4; j++) {
                int w = threadIdx.x * 4 + j;
                if (w < mask_words) {
                    unsigned int v = mw[w];
                    if (v > 1u) iok = 0;
                    if (v != 0u && v != 0x3F800000u) fok = 0;
                }
            }
            if (!iok) atomicAnd(&s_int_ok, 0);
            if (!fok) atomicAnd(&s_float_ok, 0);
        }
        __syncthreads();
        if (threadIdx.x == 0) g_mask_kind = s_int_ok ? 0 : (s_float_ok ? 2 : 1);
    }
}

// ---------------- B chunk prefetch (8KB = 64 codes x 64 dims fp16) ----------
static __device__ __forceinline__ void prefetch_B(char* smem, int buf, int nc, int kc, int tid) {
    uint32_t dst_base = smem_u32(smem + OFF_B + buf * 8192);
    #pragma unroll
    for (int j = 0; j < 2; j++) {
        int id = tid + NTHREADS * j;   // 512 granules: [n 64][g 8]
        int n  = id >> 3;
        int g  = id & 7;
        const unsigned char* src = (const unsigned char*)g_cbF
            + (size_t)(nc * 64 + n) * 512 + kc * 128 + g * 16;
        uint32_t dst = dst_base + n * 128 + ((g ^ (n & 7)) << 4);
        CP_ASYNC16(dst, src);
    }
    CP_COMMIT();
}

// top-3 insert, strict < (exact ties produce gap 0 -> handled by fp32 fallback)
#define TOP3_INS(s, v, idx) do { \
    float _v = (v); int _i = (idx); \
    if (_v < m3[s]) { \
        if (_v < m2[s]) { \
            if (_v < m1[s]) { m3[s] = m2[s]; m2[s] = m1[s]; j2[s] = j1[s]; m1[s] = _v; j1[s] = _i; } \
            else            { m3[s] = m2[s]; m2[s] = _v; j2[s] = _i; } \
        } else m3[s] = _v; \
    } \
} while (0)

// ---------------- main fused kernel -----------------------------------------
__global__ __launch_bounds__(NTHREADS, 4)
void vq_mma_kernel(const float* __restrict__ z,
                   const void* __restrict__ mask,
                   const float* __restrict__ cb,
                   float* __restrict__ out,
                   long long BND, int T, int write_idx, int write_loss) {
    extern __shared__ __align__(1024) char smem[];
    const uint32_t sb = smem_u32(smem);
    const int tid = threadIdx.x, w = tid >> 5, lane = tid & 31;
    const long long tbase = (long long)blockIdx.x * TILE_M;

    float* s_esq = (float*)(smem + OFF_ESQ);
    float* s_v1  = (float*)(smem + OFF_V1);
    float* s_v2  = (float*)(smem + OFF_V2);
    float* s_v3  = (float*)(smem + OFF_V3);
    int*   s_i1  = (int*)  (smem + OFF_I1);
    int*   s_i2  = (int*)  (smem + OFF_I2);
    float* s_zsq = (float*)(smem + OFF_ZSQ);
    float* s_mv  = (float*)(smem + OFF_MV);
    int*   s_nfl = (int*)  (smem + OFF_NFL);
    int*   s_fls = (int*)  (smem + OFF_FLIST);
    int*   s_fle = (int*)  (smem + OFF_FLE);
    float* s_rv  = (float*)(smem + OFF_RV);
    int*   s_ri  = (int*)  (smem + OFF_RI);
    float* s_zrow= (float*)(smem + OFF_ZROW);
    int*   s_last= (int*)  (smem + OFF_LAST);
    float* s_tmp = (float*)(smem + OFF_ZROW);  // pre-mainloop scratch (B buf0, pre-prefetch)

    // ---- convert z tile (64 rows) -> swizzled fp16 smem; z_sq ----
    // NOTE: uses s_tmp (B region) BEFORE the first prefetch lands is unsafe;
    // use V arrays as scratch instead (written later).
    {
        const int r = tid >> 2, h = tid & 3;
        const float4* zr = (const float4*)(z + (tbase + r) * D_DIM);
        float zs = 0.f;
        #pragma unroll
        for (int j = 0; j < 8; j++) {
            int k0 = h * 64 + j * 8;
            float4 q0 = zr[k0 / 4], q1 = zr[k0 / 4 + 1];
            float vs[8] = { q0.x, q0.y, q0.z, q0.w, q1.x, q1.y, q1.z, q1.w };
            unsigned short hs[8];
            #pragma unroll
            for (int e = 0; e < 8; e++) {
                __half hh = __float2half_rn(vs[e]);
                hs[e] = *reinterpret_cast<unsigned short*>(&hh);
                zs += vs[e] * vs[e];
            }
            uint4 H;
            H.x = (uint32_t)hs[0] | ((uint32_t)hs[1] << 16);
            H.y = (uint32_t)hs[2] | ((uint32_t)hs[3] << 16);
            H.z = (uint32_t)hs[4] | ((uint32_t)hs[5] << 16);
            H.w = (uint32_t)hs[6] | ((uint32_t)hs[7] << 16);
            int g  = h * 8 + j;
            int gp = g ^ (r & 7);
            *(uint4*)(smem + OFF_A + r * 512 + gp * 16) = H;
        }
        // stash partial z_sq in V1/V2 region (256 floats across V1+V2)
        ((float*)(smem + OFF_V1))[tid] = zs;
    }

    prefetch_B(smem, 0, 0, 0, tid);

    // stage esq
    s_esq[tid] = g_esq[tid];
    s_esq[256 + tid] = g_esq[256 + tid];
    __syncthreads();
    if (tid < TILE_M) {
        float* p = (float*)(smem + OFF_V1);
        s_zsq[tid] = p[4 * tid] + p[4 * tid + 1] + p[4 * tid + 2] + p[4 * tid + 3];
    }

    // ---- warp roles: rq = row quarter (16 rows), nhalf = code half ---------
    const int rq = w & 3, nhalf = w >> 2;
    const int arow = rq * 16 + (lane & 15);
    const uint32_t aBase = sb + OFF_A + arow * 512;
    const int aXor = arow & 7, aQ = lane >> 4;
    const int bn = (lane & 7) + ((lane >= 16) ? 8 : 0);
    const int bQ = (lane >> 3) & 1;
    const int n0row = nhalf * 32 + bn;

    float m1[2], m2[2], m3[2]; int j1[2], j2[2];
    #pragma unroll
    for (int s = 0; s < 2; s++) { m1[s] = 3.0e38f; m2[s] = 3.0e38f; m3[s] = 3.0e38f; j1[s] = 0; j2[s] = 0; }

    for (int ncl = 0; ncl < 8; ncl++) {
        float d[4][4];
        #pragma unroll
        for (int u = 0; u < 4; u++)
            #pragma unroll
            for (int q = 0; q < 4; q++) d[u][q] = 0.f;

        for (int kc = 0; kc < 4; kc++) {
            int ci = ncl * 4 + kc;
            if (ci < 31) {
                int cn = ci + 1;
                prefetch_B(smem, cn & 1, cn >> 2, cn & 3, tid);
                CP_WAIT1();
            } else {
                CP_WAIT0();
            }
            __syncthreads();
            const uint32_t bBuf = sb + OFF_B + (ci & 1) * 8192;

            #pragma unroll
            for (int ks = 0; ks < 4; ks++) {
                int gA = ((kc * 8 + ks * 2 + aQ) ^ aXor) << 4;
                uint32_t a0, a1, a2, a3;
                LDSM_X4(a0, a1, a2, a3, aBase + gA);
                uint32_t baddr = bBuf + n0row * 128 + (((ks * 2 + bQ) ^ (n0row & 7)) << 4);
                uint32_t b0, b1, b2, b3, e0r, e1r, e2r, e3r;
                LDSM_X4(b0, b1, b2, b3, baddr);
                LDSM_X4(e0r, e1r, e2r, e3r, baddr + 2048);   // +16 codes, same xor
                MMA_F16(d[0], a0, a1, a2, a3, b0, b1);
                MMA_F16(d[1], a0, a1, a2, a3, b2, b3);
                MMA_F16(d[2], a0, a1, a2, a3, e0r, e1r);
                MMA_F16(d[3], a0, a1, a2, a3, e2r, e3r);
            }
            __syncthreads();
        }

        // fold chunk into top-3 (ascending code order)
        #pragma unroll
        for (int ct = 0; ct < 4; ct++) {
            int c0 = ncl * 64 + nhalf * 32 + ct * 8 + 2 * (lane & 3);
            TOP3_INS(0, fmaf(-2.f, d[ct][0], s_esq[c0]),     c0);
            TOP3_INS(0, fmaf(-2.f, d[ct][1], s_esq[c0 + 1]), c0 + 1);
            TOP3_INS(1, fmaf(-2.f, d[ct][2], s_esq[c0]),     c0);
            TOP3_INS(1, fmaf(-2.f, d[ct][3], s_esq[c0 + 1]), c0 + 1);
        }
    }

    // quad reduce (merge top-3 across the 4 lanes of each row)
    #pragma unroll
    for (int msk = 1; msk <= 2; msk <<= 1) {
        #pragma unroll
        for (int s = 0; s < 2; s++) {
            float o1 = __shfl_xor_sync(0xFFFFFFFFu, m1[s], msk);
            int   p1 = __shfl_xor_sync(0xFFFFFFFFu, j1[s], msk);
            float o2 = __shfl_xor_sync(0xFFFFFFFFu, m2[s], msk);
            int   p2 = __shfl_xor_sync(0xFFFFFFFFu, j2[s], msk);
            float o3 = __shfl_xor_sync(0xFFFFFFFFu, m3[s], msk);
            TOP3_INS(s, o1, p1);
            TOP3_INS(s, o2, p2);
            if (o3 < m3[s]) m3[s] = o3;
        }
    }
    if (tid == 0) { s_nfl[0] = 0; s_nfl[1] = 0; }   // B region now dead
    if ((lane & 3) == 0) {
        #pragma unroll
        for (int s = 0; s < 2; s++) {
            int r = rq * 16 + s * 8 + (lane >> 2);
            int idx = nhalf * 64 + r;
            s_v1[idx] = m1[s]; s_v2[idx] = m2[s]; s_v3[idx] = m3[s];
            s_i1[idx] = j1[s]; s_i2[idx] = j2[s];
        }
    }
    __syncthreads();

    // final per-row merge of the two code halves + fallback classification
    if (tid < TILE_M) {
        float a1 = s_v1[tid], a2 = s_v2[tid], a3 = s_v3[tid];
        int   b1 = s_i1[tid], b2 = s_i2[tid];
        float o1 = s_v1[64 + tid], o2 = s_v2[64 + tid], o3 = s_v3[64 + tid];
        int   p1 = s_i1[64 + tid], p2 = s_i2[64 + tid];
        if (o1 < a1) { a3 = a2; a2 = a1; b2 = b1; a1 = o1; b1 = p1; }
        else if (o1 < a2) { a3 = a2; a2 = o1; b2 = p1; }
        else if (o1 < a3) a3 = o1;
        if (o2 < a1) { a3 = a2; a2 = a1; b2 = b1; a1 = o2; b1 = p2; }
        else if (o2 < a2) { a3 = a2; a2 = o2; b2 = p2; }
        else if (o2 < a3) a3 = o2;
        if (o3 < a3) a3 = o3;
        s_v1[tid] = a1; s_i1[tid] = b1; s_i2[tid] = b2;
        if (a3 - a1 < T_CHEAP) {
            int p = atomicAdd(&s_nfl[1], 1);
            if (p < 64) s_fle[p] = tid;
        } else if (a2 - a1 < T_CHEAP) {
            int p = atomicAdd(&s_nfl[0], 1);
            if (p < 64) s_fls[p] = tid;
        }
    }
    __syncthreads();

    // ---- cheap fallback: exact fp32 for {i1, i2} only (one warp per token) --
    {
        int nf = s_nfl[0]; if (nf > 64) nf = 64;
        for (int f = w; f < nf; f += 8) {
            int t = s_fls[f];
            int k1 = s_i1[t], k2 = s_i2[t];
            const float4* zr = (const float4*)(z + (tbase + t) * D_DIM);
            float4 za = zr[lane * 2], zb = zr[lane * 2 + 1];
            const float4* r1 = (const float4*)(cb + (size_t)k1 * D_DIM);
            const float4* r2 = (const float4*)(cb + (size_t)k2 * D_DIM);
            float4 ea = r1[lane * 2], eb = r1[lane * 2 + 1];
            float4 fa = r2[lane * 2], fb = r2[lane * 2 + 1];
            float d1 = za.x*ea.x + za.y*ea.y + za.z*ea.z + za.w*ea.w
                     + zb.x*eb.x + zb.y*eb.y + zb.z*eb.z + zb.w*eb.w;
            float d2 = za.x*fa.x + za.y*fa.y + za.z*fa.z + za.w*fa.w
                     + zb.x*fb.x + zb.y*fb.y + zb.z*fb.z + zb.w*fb.w;
            #pragma unroll
            for (int m = 16; m >= 1; m >>= 1) {
                d1 += __shfl_xor_sync(0xFFFFFFFFu, d1, m);
                d2 += __shfl_xor_sync(0xFFFFFFFFu, d2, m);
            }
            if (lane == 0) {
                float sc1 = s_esq[k1] - 2.f * d1;
                float sc2 = s_esq[k2] - 2.f * d2;
                if (sc2 < sc1 || (sc2 == sc1 && k2 < k1)) { s_i1[t] = k2; s_v1[t] = sc2; }
                else s_v1[t] = sc1;
            }
        }
    }
    __syncthreads();

    // ---- expensive fallback: full exact rescan (rare) -----------------------
    {
        int ne = s_nfl[1]; if (ne > 64) ne = 64;
        for (int f = 0; f < ne; f++) {
            int t = s_fle[f];
            s_zrow[tid] = z[(tbase + t) * D_DIM + tid];
            __syncthreads();
            float best = 3.0e38f; int bi = 0;
            #pragma unroll 1
            for (int rep = 0; rep < 2; rep++) {
                int k = tid + rep * 256;
                const float4* crow = (const float4*)(cb + (size_t)k * D_DIM);
                const float4* zr4 = (const float4*)s_zrow;
                float acc = 0.f;
                #pragma unroll 8
                for (int q = 0; q < 64; q++) {
                    float4 a = zr4[q]; float4 b = crow[q];
                    acc += a.x * b.x + a.y * b.y + a.z * b.z + a.w * b.w;
                }
                float sc = s_esq[k] - 2.0f * acc;
                if (sc < best || (sc == best && k < bi)) { best = sc; bi = k; }
            }
            s_rv[tid] = best; s_ri[tid] = bi;
            __syncthreads();
            for (int st = 128; st > 0; st >>= 1) {
                if (tid < st) {
                    float ov = s_rv[tid + st]; int oi = s_ri[tid + st];
                    if (ov < s_rv[tid] || (ov == s_rv[tid] && oi < s_ri[tid])) {
                        s_rv[tid] = ov; s_ri[tid] = oi;
                    }
                }
                __syncthreads();
            }
            if (tid == 0) { s_i1[t] = s_ri[0]; s_v1[t] = s_rv[0]; }
            __syncthreads();
        }
    }

    // ---- epilogue: mask, indices, quantized ----
    const int mkind = g_mask_kind;
    if (tid < TILE_M) {
        long long gt = tbase + tid;
        float mval;
        if (mkind == 0)      mval = ((const int*)mask)[gt] ? 1.f : 0.f;
        else if (mkind == 1) mval = ((const unsigned char*)mask)[gt] ? 1.f : 0.f;
        else                 mval = ((const float*)mask)[gt];
        s_mv[tid] = mval;
        if (write_idx)
            out[(long long)T * D_DIM + gt] = (mval != 0.f) ? (float)s_i1[tid] : -1.0f;
    }
    __syncthreads();
    {
        const int rg = tid >> 7, col = tid & 127;
        float2* out2 = (float2*)out;
        #pragma unroll 4
        for (int u = 0; u < 32; u++) {
            int t = rg * 32 + u;
            int k = s_i1[t];
            float mv = s_mv[t];
            float2 e = ((const float2*)(cb + (size_t)k * D_DIM))[col];
            out2[(tbase + t) * (D_DIM / 2) + col] = make_float2(e.x * mv, e.y * mv);
        }
    }

    // ---- fused loss ----
    if (write_loss) {
        if (tid < TILE_M) s_rv[tid] = s_zsq[tid] + s_v1[tid];
        __syncthreads();
        for (int st = 32; st > 0; st >>= 1) {
            if (tid < st) s_rv[tid] += s_rv[tid + st];
            __syncthreads();
        }
        if (tid == 0) {
            g_partials[blockIdx.x] = s_rv[0];
            __threadfence();
            unsigned int tk = atomicAdd(&g_ticket, 1u);
            *s_last = (tk == (unsigned int)(gridDim.x - 1)) ? 1 : 0;
        }
        __syncthreads();
        if (*s_last) {
            __threadfence();
            float v = 0.f;
            #pragma unroll
            for (int j = 0; j < 4; j++) v += g_partials[tid + 256 * j];
            s_rv[tid] = v;
            __syncthreads();
            for (int st = 128; st > 0; st >>= 1) {
                if (tid < st) s_rv[tid] += s_rv[tid + st];
                __syncthreads();
            }
            if (tid == 0) {
                out[BND + T] = 0.25f * s_rv[0] / (float)BND;
                g_ticket = 0;
            }
        }
    }
}

// ---------------------------------------------------------------------------
extern "C" void kernel_launch(void* const* d_in, const int* in_sizes, int n_in,
                              void* d_out, int out_size) {
    const float* z    = (const float*)d_in[0];
    const void*  mask = d_in[1];
    const float* cb   = (const float*)d_in[2];
    float* out = (float*)d_out;

    long long BND = in_sizes[0];     // 16777216
    int T = in_sizes[1];             // 65536

    cudaFuncSetAttribute(vq_mma_kernel, cudaFuncAttributeMaxDynamicSharedMemorySize, SMEM_TOTAL);

    int mask_words = (T / 4 < 1024) ? (T / 4) : 1024;
    prep_kernel<<<32, 512>>>(cb, mask, mask_words);

    int write_idx  = ((long long)out_size >= BND + T) ? 1 : 0;
    int write_loss = ((long long)out_size >= BND + T + 1) ? 1 : 0;

    vq_mma_kernel<<<NTILES, NTHREADS, SMEM_TOTAL>>>(z, mask, cb, out, BND, T, write_idx, write_loss);
}

// round 12
// speedup vs baseline: 1.1504x; 1.1504x over previous
#include <cuda_runtime.h>
#include <cuda_fp16.h>
#include <cstdint>

#define D_DIM    256
#define K_DIM    512
#define TILE_M   64
#define NTILES   1024
#define NTHREADS 128
#define T_CHEAP  0.10f

// ---------------- device globals (no runtime allocs) ------------------------
__device__ __align__(16) unsigned short g_cbF[K_DIM * D_DIM];  // fp16 codebook
__device__ float g_esq[K_DIM];
__device__ float g_partials[NTILES];
__device__ unsigned int g_ticket;
__device__ int   g_mask_kind;   // 0=int32, 1=uint8, 2=float32

// ---------------- smem layout ------------------------------------------------
#define OFF_A     0          // z fp16: 64 rows x 512B (swizzled) = 32KB
#define OFF_B     32768      // 2 bufs x 16KB (64 codes x 128 dims each)
#define OFF_ESQ   65536      // 512 f
#define OFF_V1    67584      // 128 f
#define OFF_V2    68096
#define OFF_V3    68608
#define OFF_I1    69120
#define OFF_I2    69632
#define OFF_ZSQ   70144      // 64 f
#define OFF_MV    70400      // 64 f
#define SMEM_TOTAL 70656
// aliases into B-buf0 (dead after the it=15 barrier; last buf0 read is it=14):
#define OFF_ZROW  (OFF_B + 0)      // 256 f
#define OFF_RV    (OFF_B + 1024)   // 128 f
#define OFF_RI    (OFF_B + 1536)   // 128 i
#define OFF_FLIST (OFF_B + 2048)   // 64 i
#define OFF_FLE   (OFF_B + 2304)   // 64 i
#define OFF_NFL   (OFF_B + 2560)   // 2 i
#define OFF_LAST  (OFF_B + 2576)   // 1 i

// ---------------- helpers ---------------------------------------------------
static __device__ __forceinline__ uint32_t smem_u32(const void* p) {
    uint32_t a;
    asm("{ .reg .u64 t; cvta.to.shared.u64 t, %1; cvt.u32.u64 %0, t; }" : "=r"(a) : "l"(p));
    return a;
}
#define LDSM_X4(r0,r1,r2,r3,addr) \
    asm volatile("ldmatrix.sync.aligned.m8n8.x4.shared.b16 {%0,%1,%2,%3}, [%4];" \
        : "=r"(r0),"=r"(r1),"=r"(r2),"=r"(r3) : "r"(addr))
#define MMA_F16(dd, a0,a1,a2,a3, b0,b1) \
    asm volatile("mma.sync.aligned.m16n8k16.row.col.f32.f16.f16.f32 " \
        "{%0,%1,%2,%3}, {%4,%5,%6,%7}, {%8,%9}, {%0,%1,%2,%3};" \
        : "+f"((dd)[0]),"+f"((dd)[1]),"+f"((dd)[2]),"+f"((dd)[3]) \
        : "r"(a0),"r"(a1),"r"(a2),"r"(a3),"r"(b0),"r"(b1))
#define CP_ASYNC16(dst, src) \
    asm volatile("cp.async.cg.shared.global [%0], [%1], 16;" :: "r"(dst), "l"(src) : "memory")
#define CP_COMMIT() asm volatile("cp.async.commit_group;" ::: "memory")
#define CP_WAIT0()  asm volatile("cp.async.wait_group 0;" ::: "memory")

// ---------------- prep: codebook fp16 + ||e||^2 + mask dtype ----------------
__global__ void prep_kernel(const float* __restrict__ cb,
                            const void* __restrict__ mask, int mask_words) {
    int warp = blockIdx.x * 16 + (threadIdx.x >> 5);
    int lane = threadIdx.x & 31;
    const float4* row = (const float4*)(cb + (size_t)warp * D_DIM);
    float4 v0 = row[lane * 2], v1 = row[lane * 2 + 1];
    float vs[8] = { v0.x, v0.y, v0.z, v0.w, v1.x, v1.y, v1.z, v1.w };
    unsigned short hs[8];
    float zs = 0.f;
    #pragma unroll
    for (int e = 0; e < 8; e++) {
        __half h = __float2half_rn(vs[e]);
        hs[e] = *reinterpret_cast<unsigned short*>(&h);
        zs += vs[e] * vs[e];
    }
    uint4 P;
    P.x = (uint32_t)hs[0] | ((uint32_t)hs[1] << 16);
    P.y = (uint32_t)hs[2] | ((uint32_t)hs[3] << 16);
    P.z = (uint32_t)hs[4] | ((uint32_t)hs[5] << 16);
    P.w = (uint32_t)hs[6] | ((uint32_t)hs[7] << 16);
    *(uint4*)(g_cbF + (size_t)warp * D_DIM + lane * 8) = P;
    #pragma unroll
    for (int m = 16; m >= 1; m >>= 1) zs += __shfl_xor_sync(0xFFFFFFFFu, zs, m);
    if (lane == 0) g_esq[warp] = zs;

    if (blockIdx.x == 0) {
        __shared__ int s_int_ok, s_float_ok;
        if (threadIdx.x == 0) { s_int_ok = 1; s_float_ok = 1; }
        __syncthreads();
        if (threadIdx.x < 256) {
            const unsigned int* mw = (const unsigned int*)mask;
            int iok = 1, fok = 1;
            for (int j = 0; j < 4; j++) {
                int w = threadIdx.x * 4 + j;
                if (w < mask_words) {
                    unsigned int v = mw[w];
                    if (v > 1u) iok = 0;
                    if (v != 0u && v != 0x3F800000u) fok = 0;
                }
            }
            if (!iok) atomicAnd(&s_int_ok, 0);
            if (!fok) atomicAnd(&s_float_ok, 0);
        }
        __syncthreads();
        if (threadIdx.x == 0) g_mask_kind = s_int_ok ? 0 : (s_float_ok ? 2 : 1);
    }
}

// ---------------- B chunk prefetch (16KB = 64 codes x 128 dims fp16) --------
// code row n: 256B, 16 granules; swizzled granule = g ^ (n & 7)
__device__ __forceinline__ void prefetch_B(char* smem, int buf, int ncl, int kh, int tid) {
    uint32_t dst_base = smem_u32(smem + OFF_B + buf * 16384);
    #pragma unroll
    for (int j = 0; j < 8; j++) {
        int id = tid + NTHREADS * j;   // 1024 granules: [n 64][g 16]
        int n  = id >> 4;
        int g  = id & 15;
        const unsigned char* src = (const unsigned char*)g_cbF
            + (size_t)(ncl * 64 + n) * 512 + kh * 256 + g * 16;
        uint32_t dst = dst_base + n * 256 + ((g ^ (n & 7)) << 4);
        CP_ASYNC16(dst, src);
    }
    CP_COMMIT();
}

// top-3 insert, strict < (exact ties -> gap 0 -> exact fp32 fallback resolves)
#define TOP3_INS(s, v, idx) do { \
    float _v = (v); int _i = (idx); \
    if (_v < m3[s]) { \
        if (_v < m2[s]) { \
            if (_v < m1[s]) { m3[s] = m2[s]; m2[s] = m1[s]; j2[s] = j1[s]; m1[s] = _v; j1[s] = _i; } \
            else            { m3[s] = m2[s]; m2[s] = _v; j2[s] = _i; } \
        } else m3[s] = _v; \
    } \
} while (0)

// ---------------- main fused kernel -----------------------------------------
__global__ __launch_bounds__(NTHREADS, 3)
void vq_mma_kernel(const float* __restrict__ z,
                   const void* __restrict__ mask,
                   const float* __restrict__ cb,
                   float* __restrict__ out,
                   long long BND, int T, int write_idx, int write_loss) {
    extern __shared__ __align__(1024) char smem[];
    const uint32_t sb = smem_u32(smem);
    const int tid = threadIdx.x, w = tid >> 5, lane = tid & 31;
    const long long tbase = (long long)blockIdx.x * TILE_M;

    float* s_esq = (float*)(smem + OFF_ESQ);
    float* s_v1  = (float*)(smem + OFF_V1);
    float* s_v2  = (float*)(smem + OFF_V2);
    float* s_v3  = (float*)(smem + OFF_V3);
    int*   s_i1  = (int*)  (smem + OFF_I1);
    int*   s_i2  = (int*)  (smem + OFF_I2);
    float* s_zsq = (float*)(smem + OFF_ZSQ);
    float* s_mv  = (float*)(smem + OFF_MV);
    int*   s_nfl = (int*)  (smem + OFF_NFL);
    int*   s_fls = (int*)  (smem + OFF_FLIST);
    int*   s_fle = (int*)  (smem + OFF_FLE);
    float* s_rv  = (float*)(smem + OFF_RV);
    int*   s_ri  = (int*)  (smem + OFF_RI);
    float* s_zrow= (float*)(smem + OFF_ZROW);
    int*   s_last= (int*)  (smem + OFF_LAST);

    // kick first B chunk immediately (overlaps A conversion)
    prefetch_B(smem, 0, 0, 0, tid);

    // stage esq
    #pragma unroll
    for (int j = 0; j < 4; j++) s_esq[tid + 128 * j] = g_esq[tid + 128 * j];

    // ---- convert z tile (64 rows) -> swizzled fp16 smem; z_sq partials -----
    {
        const int r = tid >> 1, h = tid & 1;
        const float4* zr = (const float4*)(z + (tbase + r) * D_DIM);
        float zs = 0.f;
        #pragma unroll 4
        for (int j = 0; j < 16; j++) {
            int k0 = h * 128 + j * 8;
            float4 q0 = zr[k0 / 4], q1 = zr[k0 / 4 + 1];
            float vs[8] = { q0.x, q0.y, q0.z, q0.w, q1.x, q1.y, q1.z, q1.w };
            unsigned short hs[8];
            #pragma unroll
            for (int e = 0; e < 8; e++) {
                __half hh = __float2half_rn(vs[e]);
                hs[e] = *reinterpret_cast<unsigned short*>(&hh);
                zs += vs[e] * vs[e];
            }
            uint4 H;
            H.x = (uint32_t)hs[0] | ((uint32_t)hs[1] << 16);
            H.y = (uint32_t)hs[2] | ((uint32_t)hs[3] << 16);
            H.z = (uint32_t)hs[4] | ((uint32_t)hs[5] << 16);
            H.w = (uint32_t)hs[6] | ((uint32_t)hs[7] << 16);
            int g  = h * 16 + j;
            int gp = g ^ (r & 7);
            *(uint4*)(smem + OFF_A + r * 512 + gp * 16) = H;
        }
        s_v1[tid] = zs;   // persistent region; consumed before argmin store
    }
    __syncthreads();
    if (tid < TILE_M) s_zsq[tid] = s_v1[2 * tid] + s_v1[2 * tid + 1];

    // ---- warp roles (R8-identical): rowgrp = w&1, nhalf = w>>1 -------------
    const int rowgrp = w & 1, nhalf = w >> 1;
    const int arow = rowgrp * 32 + (lane & 15);
    const uint32_t aBase0 = sb + OFF_A + arow * 512;
    const uint32_t aBase1 = aBase0 + 16 * 512;          // +16 rows, same xor class
    const int aXor = arow & 7, aQ = lane >> 4;
    const int bn = (lane & 7) + ((lane >= 16) ? 8 : 0);
    const int bQ = (lane >> 3) & 1;
    const int n0row = nhalf * 32 + bn;                  // code row within 64-chunk

    float m1[4], m2[4], m3[4]; int j1[4], j2[4];
    #pragma unroll
    for (int s = 0; s < 4; s++) { m1[s] = 3.0e38f; m2[s] = 3.0e38f; m3[s] = 3.0e38f; j1[s] = 0; j2[s] = 0; }

    // mainloop: 8 code-chunks x 2 dim-halves = 16 iterations, ONE barrier each
    for (int ncl = 0; ncl < 8; ncl++) {
        float d[8][4];
        #pragma unroll
        for (int u = 0; u < 8; u++)
            #pragma unroll
            for (int q = 0; q < 4; q++) d[u][q] = 0.f;

        #pragma unroll
        for (int kh = 0; kh < 2; kh++) {
            const int it = ncl * 2 + kh;
            CP_WAIT0();
            __syncthreads();   // buf(it&1) full everywhere; all reads of other buf done
            if (it < 15) {
                const int it2 = it + 1;
                prefetch_B(smem, it2 & 1, it2 >> 1, it2 & 1, tid);
            }
            const uint32_t bBuf = sb + OFF_B + (it & 1) * 16384;

            #pragma unroll
            for (int ksl = 0; ksl < 8; ksl++) {
                int gA = ((kh * 16 + ksl * 2 + aQ) ^ aXor) << 4;
                uint32_t a0, a1, a2, a3, c0r, c1r, c2r, c3r;
                LDSM_X4(a0, a1, a2, a3, aBase0 + gA);
                LDSM_X4(c0r, c1r, c2r, c3r, aBase1 + gA);
                uint32_t baddr = bBuf + n0row * 256 + (((ksl * 2 + bQ) ^ (n0row & 7)) << 4);
                uint32_t b0, b1, b2, b3, e0r, e1r, e2r, e3r;
                LDSM_X4(b0, b1, b2, b3, baddr);
                LDSM_X4(e0r, e1r, e2r, e3r, baddr + 4096);   // +16 code rows, same xor class
                // u = rt*4 + nt*2 + h  (rt = A m16 tile, nt = B 16-code group, h = n8 half)
                MMA_F16(d[0], a0, a1, a2, a3, b0, b1);
                MMA_F16(d[1], a0, a1, a2, a3, b2, b3);
                MMA_F16(d[2], a0, a1, a2, a3, e0r, e1r);
                MMA_F16(d[3], a0, a1, a2, a3, e2r, e3r);
                MMA_F16(d[4], c0r, c1r, c2r, c3r, b0, b1);
                MMA_F16(d[5], c0r, c1r, c2r, c3r, b2, b3);
                MMA_F16(d[6], c0r, c1r, c2r, c3r, e0r, e1r);
                MMA_F16(d[7], c0r, c1r, c2r, c3r, e2r, e3r);
            }
        }

        // fold chunk into top-3 — R8's exact 4-slot mapping:
        // slot rt*2   <- acc c0/c1 (row lane>>2),  slot rt*2+1 <- acc c2/c3 (row +8)
        #pragma unroll
        for (int u = 0; u < 8; u++) {
            int rt = u >> 2, nt = (u >> 1) & 1, h = u & 1;
            int c0 = ncl * 64 + nhalf * 32 + nt * 16 + h * 8 + 2 * (lane & 3);
            float e0 = s_esq[c0], e1 = s_esq[c0 + 1];
            int sA = rt * 2, sB = rt * 2 + 1;
            TOP3_INS(sA, fmaf(-2.f, d[u][0], e0), c0);
            TOP3_INS(sA, fmaf(-2.f, d[u][1], e1), c0 + 1);
            TOP3_INS(sB, fmaf(-2.f, d[u][2], e0), c0);
            TOP3_INS(sB, fmaf(-2.f, d[u][3], e1), c0 + 1);
        }
    }

    // quad reduce (merge top-3 across the 4 lanes sharing each output row)
    #pragma unroll
    for (int msk = 1; msk <= 2; msk <<= 1) {
        #pragma unroll
        for (int s = 0; s < 4; s++) {
            float o1 = __shfl_xor_sync(0xFFFFFFFFu, m1[s], msk);
            int   p1 = __shfl_xor_sync(0xFFFFFFFFu, j1[s], msk);
            float o2 = __shfl_xor_sync(0xFFFFFFFFu, m2[s], msk);
            int   p2 = __shfl_xor_sync(0xFFFFFFFFu, j2[s], msk);
            float o3 = __shfl_xor_sync(0xFFFFFFFFu, m3[s], msk);
            TOP3_INS(s, o1, p1);
            TOP3_INS(s, o2, p2);
            if (o3 < m3[s]) m3[s] = o3;
        }
    }
    if (tid == 0) { s_nfl[0] = 0; s_nfl[1] = 0; }   // B-buf0 dead since it=15 barrier
    if ((lane & 3) == 0) {
        #pragma unroll
        for (int s = 0; s < 4; s++) {
            int r = rowgrp * 32 + (s >> 1) * 16 + (s & 1) * 8 + (lane >> 2);
            int idx = nhalf * 64 + r;
            s_v1[idx] = m1[s]; s_v2[idx] = m2[s]; s_v3[idx] = m3[s];
            s_i1[idx] = j1[s]; s_i2[idx] = j2[s];
        }
    }
    __syncthreads();

    // final per-row merge of the two code halves + fallback classification
    if (tid < TILE_M) {
        float a1 = s_v1[tid], a2 = s_v2[tid], a3 = s_v3[tid];
        int   b1 = s_i1[tid], b2 = s_i2[tid];
        float o1 = s_v1[64 + tid], o2 = s_v2[64 + tid], o3 = s_v3[64 + tid];
        int   p1 = s_i1[64 + tid], p2 = s_i2[64 + tid];
        if (o1 < a1) { a3 = a2; a2 = a1; b2 = b1; a1 = o1; b1 = p1; }
        else if (o1 < a2) { a3 = a2; a2 = o1; b2 = p1; }
        else if (o1 < a3) a3 = o1;
        if (o2 < a1) { a3 = a2; a2 = a1; b2 = b1; a1 = o2; b1 = p2; }
        else if (o2 < a2) { a3 = a2; a2 = o2; b2 = p2; }
        else if (o2 < a3) a3 = o2;
        if (o3 < a3) a3 = o3;
        s_v1[tid] = a1; s_i1[tid] = b1; s_i2[tid] = b2;
        if (a3 - a1 < T_CHEAP) {
            int p = atomicAdd(&s_nfl[1], 1);
            if (p < 64) s_fle[p] = tid;
        } else if (a2 - a1 < T_CHEAP) {
            int p = atomicAdd(&s_nfl[0], 1);
            if (p < 64) s_fls[p] = tid;
        }
    }
    __syncthreads();

    // ---- cheap fallback: exact fp32 for {i1, i2} only (one warp per token) --
    {
        int nf = s_nfl[0]; if (nf > 64) nf = 64;
        for (int f = w; f < nf; f += 4) {
            int t = s_fls[f];
            int k1 = s_i1[t], k2 = s_i2[t];
            const float4* zr = (const float4*)(z + (tbase + t) * D_DIM);
            float4 za = zr[lane * 2], zb = zr[lane * 2 + 1];
            const float4* r1 = (const float4*)(cb + (size_t)k1 * D_DIM);
            const float4* r2 = (const float4*)(cb + (size_t)k2 * D_DIM);
            float4 ea = r1[lane * 2], eb = r1[lane * 2 + 1];
            float4 fa = r2[lane * 2], fb = r2[lane * 2 + 1];
            float d1 = za.x*ea.x + za.y*ea.y + za.z*ea.z + za.w*ea.w
                     + zb.x*eb.x + zb.y*eb.y + zb.z*eb.z + zb.w*eb.w;
            float d2 = za.x*fa.x + za.y*fa.y + za.z*fa.z + za.w*fa.w
                     + zb.x*fb.x + zb.y*fb.y + zb.z*fb.z + zb.w*fb.w;
            #pragma unroll
            for (int m = 16; m >= 1; m >>= 1) {
                d1 += __shfl_xor_sync(0xFFFFFFFFu, d1, m);
                d2 += __shfl_xor_sync(0xFFFFFFFFu, d2, m);
            }
            if (lane == 0) {
                float sc1 = s_esq[k1] - 2.f * d1;
                float sc2 = s_esq[k2] - 2.f * d2;
                if (sc2 < sc1 || (sc2 == sc1 && k2 < k1)) { s_i1[t] = k2; s_v1[t] = sc2; }
                else s_v1[t] = sc1;
            }
        }
    }
    __syncthreads();

    // ---- expensive fallback: full exact rescan (rare) -----------------------
    {
        int ne = s_nfl[1]; if (ne > 64) ne = 64;
        for (int f = 0; f < ne; f++) {
            int t = s_fle[f];
            s_zrow[tid] = z[(tbase + t) * D_DIM + tid];
            s_zrow[tid + 128] = z[(tbase + t) * D_DIM + tid + 128];
            __syncthreads();
            float best = 3.0e38f; int bi = 0;
            #pragma unroll 1
            for (int rep = 0; rep < 4; rep++) {
                int k = tid + rep * 128;
                const float4* crow = (const float4*)(cb + (size_t)k * D_DIM);
                const float4* zr4 = (const float4*)s_zrow;
                float acc = 0.f;
                #pragma unroll 8
                for (int q = 0; q < 64; q++) {
                    float4 a = zr4[q]; float4 b = crow[q];
                    acc += a.x * b.x + a.y * b.y + a.z * b.z + a.w * b.w;
                }
                float sc = s_esq[k] - 2.0f * acc;
                if (sc < best || (sc == best && k < bi)) { best = sc; bi = k; }
            }
            s_rv[tid] = best; s_ri[tid] = bi;
            __syncthreads();
            for (int st = 64; st > 0; st >>= 1) {
                if (tid < st) {
                    float ov = s_rv[tid + st]; int oi = s_ri[tid + st];
                    if (ov < s_rv[tid] || (ov == s_rv[tid] && oi < s_ri[tid])) {
                        s_rv[tid] = ov; s_ri[tid] = oi;
                    }
                }
                __syncthreads();
            }
            if (tid == 0) { s_i1[t] = s_ri[0]; s_v1[t] = s_rv[0]; }
            __syncthreads();
        }
    }

    // ---- epilogue: mask, indices, quantized ----
    const int mkind = g_mask_kind;
    if (tid < TILE_M) {
        long long gt = tbase + tid;
        float mval;
        if (mkind == 0)      mval = ((const int*)mask)[gt] ? 1.f : 0.f;
        else if (mkind == 1) mval = ((const unsigned char*)mask)[gt] ? 1.f : 0.f;
        else                 mval = ((const float*)mask)[gt];
        s_mv[tid] = mval;
        if (write_idx)
            out[(long long)T * D_DIM + gt] = (mval != 0.f) ? (float)s_i1[tid] : -1.0f;
    }
    __syncthreads();
    {
        float2* out2 = (float2*)out;
        #pragma unroll 4
        for (int t = 0; t < TILE_M; t++) {
            int k = s_i1[t];
            float mv = s_mv[t];
            float2 e = ((const float2*)(cb + (size_t)k * D_DIM))[tid];
            out2[(tbase + t) * (D_DIM / 2) + tid] = make_float2(e.x * mv, e.y * mv);
        }
    }

    // ---- fused loss ----
    if (write_loss) {
        if (tid < TILE_M) s_rv[tid] = s_zsq[tid] + s_v1[tid];
        __syncthreads();
        for (int st = 32; st > 0; st >>= 1) {
            if (tid < st) s_rv[tid] += s_rv[tid + st];
            __syncthreads();
        }
        if (tid == 0) {
            g_partials[blockIdx.x] = s_rv[0];
            __threadfence();
            unsigned int tk = atomicAdd(&g_ticket, 1u);
            *s_last = (tk == (unsigned int)(gridDim.x - 1)) ? 1 : 0;
        }
        __syncthreads();
        if (*s_last) {
            __threadfence();
            float v = 0.f;
            #pragma unroll
            for (int j = 0; j < 8; j++) v += g_partials[tid + 128 * j];
            s_rv[tid] = v;
            __syncthreads();
            for (int st = 64; st > 0; st >>= 1) {
                if (tid < st) s_rv[tid] += s_rv[tid + st];
                __syncthreads();
            }
            if (tid == 0) {
                out[BND + T] = 0.25f * s_rv[0] / (float)BND;
                g_ticket = 0;
            }
        }
    }
}

// ---------------------------------------------------------------------------
extern "C" void kernel_launch(void* const* d_in, const int* in_sizes, int n_in,
                              void* d_out, int out_size) {
    const float* z    = (const float*)d_in[0];
    const void*  mask = d_in[1];
    const float* cb   = (const float*)d_in[2];
    float* out = (float*)d_out;

    long long BND = in_sizes[0];     // 16777216
    int T = in_sizes[1];             // 65536

    cudaFuncSetAttribute(vq_mma_kernel, cudaFuncAttributeMaxDynamicSharedMemorySize, SMEM_TOTAL);

    int mask_words = (T / 4 < 1024) ? (T / 4) : 1024;
    prep_kernel<<<32, 512>>>(cb, mask, mask_words);

    int write_idx  = ((long long)out_size >= BND + T) ? 1 : 0;
    int write_loss = ((long long)out_size >= BND + T + 1) ? 1 : 0;

    vq_mma_kernel<<<NTILES, NTHREADS, SMEM_TOTAL>>>(z, mask, cb, out, BND, T, write_idx, write_loss);
}